// round 2
// baseline (speedup 1.0000x reference)
#include <cuda_runtime.h>
#include <math.h>

#define FIN 128
#define HH  64
#define MAXN 100000
#define MAXE 1600000

// ---- device scratch (allocation-free rule: __device__ globals) ----
__device__ float g_h1[MAXN * HH];   // relu(x@W1^T + b1)
__device__ float g_k [MAXN * HH];   // fused key   = Ak@h1 + ck
__device__ float g_q [MAXN * HH];   // fused query = Aq@h1 + cq
__device__ float g_vw[MAXN * HH];   // fused value pre-scaled by Wsc
__device__ float g_AkT[HH * HH];    // [m][f] layout (transposed for conflict-free LDS)
__device__ float g_AqT[HH * HH];
__device__ float g_AvT[HH * HH];
__device__ float g_u  [HH];         // u[m] = sum_f Wsc[f] * (Ws@W2)[f][m]
__device__ float g_ck [HH];
__device__ float g_cq [HH];
__device__ float g_cv [HH];
__device__ float g_c0 [1];          // scalar const of score

// ============================================================
// Prep: fold W2 into projections. 4 blocks, one per matrix/task.
// ============================================================
__global__ void prep_kernel(const float* __restrict__ W2, const float* __restrict__ b2,
                            const float* __restrict__ Wk, const float* __restrict__ bk,
                            const float* __restrict__ Wq, const float* __restrict__ bq,
                            const float* __restrict__ Wv, const float* __restrict__ bv,
                            const float* __restrict__ Ws, const float* __restrict__ bg,
                            const float* __restrict__ Wsc, const float* __restrict__ bsc)
{
    __shared__ float WaT[HH * HH];   // [o][f]
    __shared__ float W2s[HH * HH];   // [o][m]
    int t = threadIdx.x;             // 256
    int b = blockIdx.x;

    if (b < 3) {
        const float* Wa  = (b == 0) ? Wk : (b == 1) ? Wq : Wv;
        const float* bia = (b == 0) ? bk : (b == 1) ? bq : bv;
        float* outA = (b == 0) ? g_AkT : (b == 1) ? g_AqT : g_AvT;
        float* outc = (b == 0) ? g_ck  : (b == 1) ? g_cq  : g_cv;

        for (int i = t; i < HH * HH; i += 256) {
            int f = i / HH, o = i % HH;
            WaT[o * HH + f] = Wa[i];     // transpose into smem
            W2s[i] = W2[i];
        }
        __syncthreads();
        for (int i = t; i < HH * HH; i += 256) {
            int m = i >> 6, f = i & 63;
            float acc = 0.f;
            #pragma unroll 8
            for (int o = 0; o < HH; o++)
                acc += WaT[o * HH + f] * W2s[o * HH + m];
            if (b == 2) acc *= Wsc[f];
            outA[m * HH + f] = acc;      // i == m*64+f
        }
        if (t < HH) {
            float acc = 0.f;
            for (int o = 0; o < HH; o++) acc += WaT[o * HH + t] * b2[o];
            acc += bia[t];
            if (b == 2) acc *= Wsc[t];
            outc[t] = acc;
        }
    } else {
        // u[m] = sum_o (sum_f Wsc[f]*Ws[f][o]) * W2[o][m]
        __shared__ float ts[HH];
        __shared__ float ps[HH];
        if (t < HH) {
            float acc = 0.f;
            for (int f = 0; f < HH; f++) acc += Wsc[f] * Ws[f * HH + t];
            ts[t] = acc;
            float inner = 0.f;
            for (int o = 0; o < HH; o++) inner += Ws[t * HH + o] * b2[o];
            ps[t] = Wsc[t] * (inner + bg[t]);
        }
        __syncthreads();
        if (t < HH) {
            float acc = 0.f;
            for (int o = 0; o < HH; o++) acc += ts[o] * W2[o * HH + t];
            g_u[t] = acc;
        }
        if (t == 0) {
            float acc = bsc[0];
            for (int f = 0; f < HH; f++) acc += ps[f];
            g_c0[0] = acc;
        }
    }
}

// ============================================================
// Kernel A: h1 = relu(x @ W1^T + b1)  [N,128]->[N,64]
// ============================================================
__global__ void mlp1_kernel(const float* __restrict__ x,
                            const float* __restrict__ W1,
                            const float* __restrict__ b1, int N)
{
    extern __shared__ float sm[];
    float* W1T = sm;                 // [j][h]  128*64
    float* xs  = sm + FIN * HH;      // [32][128]
    int t = threadIdx.x;

    for (int i = t; i < HH * FIN; i += 256) {
        int h = i / FIN, j = i % FIN;
        W1T[j * HH + h] = W1[i];
    }

    int p = t & 31, g = t >> 5;
    float bA = b1[2 * p], bB = b1[2 * p + 1];
    int ntiles = (N + 31) >> 5;

    for (int tile = blockIdx.x; tile < ntiles; tile += gridDim.x) {
        int n0 = tile << 5;
        __syncthreads();
        for (int i = t; i < 32 * FIN; i += 256) {
            int n = n0 + (i >> 7);
            xs[i] = (n < N) ? x[(size_t)n * FIN + (i & 127)] : 0.f;
        }
        __syncthreads();

        float a0A=bA,a0B=bB,a1A=bA,a1B=bB,a2A=bA,a2B=bB,a3A=bA,a3B=bB;
        const float* x0 = xs + (4 * g + 0) * FIN;
        const float* x1 = xs + (4 * g + 1) * FIN;
        const float* x2 = xs + (4 * g + 2) * FIN;
        const float* x3 = xs + (4 * g + 3) * FIN;

        #pragma unroll 4
        for (int j = 0; j < FIN; j++) {
            float2 w = ((const float2*)(W1T + j * HH))[p];
            float v0 = x0[j], v1 = x1[j], v2 = x2[j], v3 = x3[j];
            a0A += w.x * v0; a0B += w.y * v0;
            a1A += w.x * v1; a1B += w.y * v1;
            a2A += w.x * v2; a2B += w.y * v2;
            a3A += w.x * v3; a3B += w.y * v3;
        }

        int nb = n0 + 4 * g;
        if (nb + 3 < N) {
            ((float2*)(g_h1 + (size_t)(nb+0)*HH))[p] = make_float2(fmaxf(a0A,0.f), fmaxf(a0B,0.f));
            ((float2*)(g_h1 + (size_t)(nb+1)*HH))[p] = make_float2(fmaxf(a1A,0.f), fmaxf(a1B,0.f));
            ((float2*)(g_h1 + (size_t)(nb+2)*HH))[p] = make_float2(fmaxf(a2A,0.f), fmaxf(a2B,0.f));
            ((float2*)(g_h1 + (size_t)(nb+3)*HH))[p] = make_float2(fmaxf(a3A,0.f), fmaxf(a3B,0.f));
        } else {
            if (nb+0 < N) ((float2*)(g_h1 + (size_t)(nb+0)*HH))[p] = make_float2(fmaxf(a0A,0.f), fmaxf(a0B,0.f));
            if (nb+1 < N) ((float2*)(g_h1 + (size_t)(nb+1)*HH))[p] = make_float2(fmaxf(a1A,0.f), fmaxf(a1B,0.f));
            if (nb+2 < N) ((float2*)(g_h1 + (size_t)(nb+2)*HH))[p] = make_float2(fmaxf(a2A,0.f), fmaxf(a2B,0.f));
            if (nb+3 < N) ((float2*)(g_h1 + (size_t)(nb+3)*HH))[p] = make_float2(fmaxf(a3A,0.f), fmaxf(a3B,0.f));
        }
    }
}

// ============================================================
// Kernel B: k,q,vw fused 64x64 projections of h1 + scorer init.
// ============================================================
__global__ void proj_kernel(float* __restrict__ out, int N)
{
    extern __shared__ float sm[];
    float* Aks = sm;
    float* Aqs = sm + HH * HH;
    float* Avs = sm + 2 * HH * HH;
    float* h1s = sm + 3 * HH * HH;      // [32][64]
    float* us  = h1s + 32 * HH;
    float* cks = us + HH;
    float* cqs = cks + HH;
    float* cvs = cqs + HH;
    int t = threadIdx.x;

    for (int i = t; i < HH * HH; i += 256) {
        Aks[i] = g_AkT[i]; Aqs[i] = g_AqT[i]; Avs[i] = g_AvT[i];
    }
    if (t < HH) { us[t] = g_u[t]; cks[t] = g_ck[t]; cqs[t] = g_cq[t]; cvs[t] = g_cv[t]; }
    __syncthreads();

    int p = t & 31, g = t >> 5;
    float c0 = g_c0[0];
    float2 ck2 = ((float2*)cks)[p], cq2 = ((float2*)cqs)[p], cv2 = ((float2*)cvs)[p];
    float2 u2  = ((float2*)us)[p];
    int ntiles = (N + 31) >> 5;

    for (int tile = blockIdx.x; tile < ntiles; tile += gridDim.x) {
        int n0 = tile << 5;
        __syncthreads();
        for (int i = t; i < 32 * HH; i += 256) {
            int n = n0 + (i >> 6);
            h1s[i] = (n < N) ? g_h1[(size_t)n0 * HH + i] : 0.f;
        }
        __syncthreads();

        float k0x=0,k0y=0,k1x=0,k1y=0,k2x=0,k2y=0,k3x=0,k3y=0;
        float q0x=0,q0y=0,q1x=0,q1y=0,q2x=0,q2y=0,q3x=0,q3y=0;
        float w0x=0,w0y=0,w1x=0,w1y=0,w2x=0,w2y=0,w3x=0,w3y=0;
        const float* h0 = h1s + (4 * g + 0) * HH;
        const float* h1p = h1s + (4 * g + 1) * HH;
        const float* h2 = h1s + (4 * g + 2) * HH;
        const float* h3 = h1s + (4 * g + 3) * HH;

        #pragma unroll 4
        for (int m = 0; m < HH; m++) {
            float2 ak = ((const float2*)(Aks + m * HH))[p];
            float2 aq = ((const float2*)(Aqs + m * HH))[p];
            float2 av = ((const float2*)(Avs + m * HH))[p];
            float v0 = h0[m], v1 = h1p[m], v2 = h2[m], v3 = h3[m];
            k0x += ak.x*v0; k0y += ak.y*v0; k1x += ak.x*v1; k1y += ak.y*v1;
            k2x += ak.x*v2; k2y += ak.y*v2; k3x += ak.x*v3; k3y += ak.y*v3;
            q0x += aq.x*v0; q0y += aq.y*v0; q1x += aq.x*v1; q1y += aq.y*v1;
            q2x += aq.x*v2; q2y += aq.y*v2; q3x += aq.x*v3; q3y += aq.y*v3;
            w0x += av.x*v0; w0y += av.y*v0; w1x += av.x*v1; w1y += av.y*v1;
            w2x += av.x*v2; w2y += av.y*v2; w3x += av.x*v3; w3y += av.y*v3;
        }

        int nb = n0 + 4 * g;
        if (nb + 3 < N) {
            ((float2*)(g_k  + (size_t)(nb+0)*HH))[p] = make_float2(k0x+ck2.x, k0y+ck2.y);
            ((float2*)(g_k  + (size_t)(nb+1)*HH))[p] = make_float2(k1x+ck2.x, k1y+ck2.y);
            ((float2*)(g_k  + (size_t)(nb+2)*HH))[p] = make_float2(k2x+ck2.x, k2y+ck2.y);
            ((float2*)(g_k  + (size_t)(nb+3)*HH))[p] = make_float2(k3x+ck2.x, k3y+ck2.y);
            ((float2*)(g_q  + (size_t)(nb+0)*HH))[p] = make_float2(q0x+cq2.x, q0y+cq2.y);
            ((float2*)(g_q  + (size_t)(nb+1)*HH))[p] = make_float2(q1x+cq2.x, q1y+cq2.y);
            ((float2*)(g_q  + (size_t)(nb+2)*HH))[p] = make_float2(q2x+cq2.x, q2y+cq2.y);
            ((float2*)(g_q  + (size_t)(nb+3)*HH))[p] = make_float2(q3x+cq2.x, q3y+cq2.y);
            ((float2*)(g_vw + (size_t)(nb+0)*HH))[p] = make_float2(w0x+cv2.x, w0y+cv2.y);
            ((float2*)(g_vw + (size_t)(nb+1)*HH))[p] = make_float2(w1x+cv2.x, w1y+cv2.y);
            ((float2*)(g_vw + (size_t)(nb+2)*HH))[p] = make_float2(w2x+cv2.x, w2y+cv2.y);
            ((float2*)(g_vw + (size_t)(nb+3)*HH))[p] = make_float2(w3x+cv2.x, w3y+cv2.y);
        } else {
            for (int d = 0; d < 4; d++) {
                int n = nb + d;
                if (n >= N) break;
                float kx = (d==0)?k0x:(d==1)?k1x:(d==2)?k2x:k3x;
                float ky = (d==0)?k0y:(d==1)?k1y:(d==2)?k2y:k3y;
                float qx = (d==0)?q0x:(d==1)?q1x:(d==2)?q2x:q3x;
                float qy = (d==0)?q0y:(d==1)?q1y:(d==2)?q2y:q3y;
                float wx = (d==0)?w0x:(d==1)?w1x:(d==2)?w2x:w3x;
                float wy = (d==0)?w0y:(d==1)?w1y:(d==2)?w2y:w3y;
                ((float2*)(g_k  + (size_t)n*HH))[p] = make_float2(kx+ck2.x, ky+ck2.y);
                ((float2*)(g_q  + (size_t)n*HH))[p] = make_float2(qx+cq2.x, qy+cq2.y);
                ((float2*)(g_vw + (size_t)n*HH))[p] = make_float2(wx+cv2.x, wy+cv2.y);
            }
        }

        // score_init: u . h1[n] + c0 -> warp-reduce (each warp owns its 4 nodes)
        float s0 = u2.x * h0[2*p]  + u2.y * h0[2*p+1];
        float s1 = u2.x * h1p[2*p] + u2.y * h1p[2*p+1];
        float s2 = u2.x * h2[2*p]  + u2.y * h2[2*p+1];
        float s3 = u2.x * h3[2*p]  + u2.y * h3[2*p+1];
        #pragma unroll
        for (int off = 16; off; off >>= 1) {
            s0 += __shfl_down_sync(0xffffffffu, s0, off);
            s1 += __shfl_down_sync(0xffffffffu, s1, off);
            s2 += __shfl_down_sync(0xffffffffu, s2, off);
            s3 += __shfl_down_sync(0xffffffffu, s3, off);
        }
        if (p == 0) {
            if (nb + 0 < N) out[nb + 0] = s0 + c0;
            if (nb + 1 < N) out[nb + 1] = s1 + c0;
            if (nb + 2 < N) out[nb + 2] = s2 + c0;
            if (nb + 3 < N) out[nb + 3] = s3 + c0;
        }
    }
}

// ============================================================
// Edge kernel: warp per edge. edge_index is INT32 (JAX x64 off).
//   out[dst] += sum_f sigmoid(k[dst][f]+q[src][f]) * vw[src][f]
// ============================================================
__global__ void edge_kernel(const int* __restrict__ ei,
                            float* __restrict__ out, int E)
{
    int lane = threadIdx.x & 31;
    int warp = (blockIdx.x * blockDim.x + threadIdx.x) >> 5;
    int nwarps = (gridDim.x * blockDim.x) >> 5;
    int per = (E + nwarps - 1) / nwarps;
    int e0 = warp * per;
    int e1 = min(E, e0 + per);

    #pragma unroll 2
    for (int e = e0; e < e1; e++) {
        int src = ei[e];
        int dst = ei[E + e];
        float2 kk = ((const float2*)(g_k  + (size_t)dst * HH))[lane];
        float2 qq = ((const float2*)(g_q  + (size_t)src * HH))[lane];
        float2 vv = ((const float2*)(g_vw + (size_t)src * HH))[lane];
        float sA = kk.x + qq.x;
        float sB = kk.y + qq.y;
        float gA = __fdividef(1.f, 1.f + __expf(-sA));
        float gB = __fdividef(1.f, 1.f + __expf(-sB));
        float acc = gA * vv.x + gB * vv.y;
        #pragma unroll
        for (int off = 16; off; off >>= 1)
            acc += __shfl_down_sync(0xffffffffu, acc, off);
        if (lane == 0) atomicAdd(out + dst, acc);
    }
}

// ============================================================
extern "C" void kernel_launch(void* const* d_in, const int* in_sizes, int n_in,
                              void* d_out, int out_size)
{
    const float* x    = (const float*)d_in[0];
    const int*   ei   = (const int*)d_in[1];      // int32! (JAX x64 disabled)
    const float* W1   = (const float*)d_in[2];
    const float* b1   = (const float*)d_in[3];
    const float* W2   = (const float*)d_in[4];
    const float* b2   = (const float*)d_in[5];
    const float* Wk   = (const float*)d_in[6];
    const float* bk   = (const float*)d_in[7];
    const float* Wq   = (const float*)d_in[8];
    const float* bq   = (const float*)d_in[9];
    const float* Wv   = (const float*)d_in[10];
    const float* bv   = (const float*)d_in[11];
    const float* Ws   = (const float*)d_in[12];
    const float* bg   = (const float*)d_in[13];
    const float* Wsc  = (const float*)d_in[14];
    const float* bsc  = (const float*)d_in[15];
    float* out = (float*)d_out;

    int N = in_sizes[0] / FIN;
    int E = in_sizes[1] / 2;

    static int attr_done = 0;
    const int mlp1_smem = (FIN * HH + 32 * FIN) * (int)sizeof(float);            // 49152
    const int proj_smem = (3 * HH * HH + 32 * HH + 4 * HH) * (int)sizeof(float); // 58368
    if (!attr_done) {
        cudaFuncSetAttribute(mlp1_kernel, cudaFuncAttributeMaxDynamicSharedMemorySize, mlp1_smem);
        cudaFuncSetAttribute(proj_kernel, cudaFuncAttributeMaxDynamicSharedMemorySize, proj_smem);
        attr_done = 1;
    }

    prep_kernel<<<4, 256>>>(W2, b2, Wk, bk, Wq, bq, Wv, bv, Ws, bg, Wsc, bsc);
    mlp1_kernel<<<592, 256, mlp1_smem>>>(x, W1, b1, N);
    proj_kernel<<<444, 256, proj_smem>>>(out, N);
    edge_kernel<<<1184, 256>>>(ei, out, E);
}

// round 3
// speedup vs baseline: 1.2250x; 1.2250x over previous
#include <cuda_runtime.h>
#include <cuda_fp16.h>
#include <math.h>

#define FIN 128
#define HH  64
#define MAXN 100000
#define MAXE 1600000

typedef unsigned long long ull;

// ---- device scratch (allocation-free rule: __device__ globals) ----
__device__ float   g_h1[MAXN * HH];    // relu(x@W1^T + b1)
__device__ __half2 g_k2 [MAXN * 32];   // fused key   (fp16, 32 half2 = 64 feats/row)
__device__ __half2 g_q2 [MAXN * 32];   // fused query
__device__ __half2 g_vw2[MAXN * 32];   // fused value pre-scaled by Wsc
__device__ float g_AkT[HH * HH];       // [m][f]
__device__ float g_AqT[HH * HH];
__device__ float g_AvT[HH * HH];
__device__ float g_u  [HH];
__device__ float g_ck [HH];
__device__ float g_cq [HH];
__device__ float g_cv [HH];
__device__ float g_c0 [1];

// ---- f32x2 packed-math helpers (sm_100+; ptxas never auto-fuses these) ----
__device__ __forceinline__ void ffma2(ull& d, ull a, ull b) {
    asm("fma.rn.f32x2 %0, %1, %2, %0;" : "+l"(d) : "l"(a), "l"(b));
}
__device__ __forceinline__ ull pack2(float x, float y) {
    ull r; asm("mov.b64 %0, {%1, %2};" : "=l"(r) : "f"(x), "f"(y)); return r;
}
__device__ __forceinline__ float2 unpack2(ull v) {
    float2 r; asm("mov.b64 {%0, %1}, %2;" : "=f"(r.x), "=f"(r.y) : "l"(v)); return r;
}
__device__ __forceinline__ float tanh_approx(float x) {
    float r; asm("tanh.approx.f32 %0, %1;" : "=f"(r) : "f"(x)); return r;
}

// ============================================================
// Prep: fold W2 into projections. 4 blocks, one per matrix/task.
// ============================================================
__global__ void prep_kernel(const float* __restrict__ W2, const float* __restrict__ b2,
                            const float* __restrict__ Wk, const float* __restrict__ bk,
                            const float* __restrict__ Wq, const float* __restrict__ bq,
                            const float* __restrict__ Wv, const float* __restrict__ bv,
                            const float* __restrict__ Ws, const float* __restrict__ bg,
                            const float* __restrict__ Wsc, const float* __restrict__ bsc)
{
    __shared__ float WaT[HH * HH];   // [o][f]
    __shared__ float W2s[HH * HH];   // [o][m]
    int t = threadIdx.x;             // 256
    int b = blockIdx.x;

    if (b < 3) {
        const float* Wa  = (b == 0) ? Wk : (b == 1) ? Wq : Wv;
        const float* bia = (b == 0) ? bk : (b == 1) ? bq : bv;
        float* outA = (b == 0) ? g_AkT : (b == 1) ? g_AqT : g_AvT;
        float* outc = (b == 0) ? g_ck  : (b == 1) ? g_cq  : g_cv;

        for (int i = t; i < HH * HH; i += 256) {
            int f = i / HH, o = i % HH;
            WaT[o * HH + f] = Wa[i];
            W2s[i] = W2[i];
        }
        __syncthreads();
        for (int i = t; i < HH * HH; i += 256) {
            int m = i >> 6, f = i & 63;
            float acc = 0.f;
            #pragma unroll 8
            for (int o = 0; o < HH; o++)
                acc += WaT[o * HH + f] * W2s[o * HH + m];
            if (b == 2) acc *= Wsc[f];
            outA[m * HH + f] = acc;
        }
        if (t < HH) {
            float acc = 0.f;
            for (int o = 0; o < HH; o++) acc += WaT[o * HH + t] * b2[o];
            acc += bia[t];
            if (b == 2) acc *= Wsc[t];
            outc[t] = acc;
        }
    } else {
        __shared__ float ts[HH];
        __shared__ float ps[HH];
        if (t < HH) {
            float acc = 0.f;
            for (int f = 0; f < HH; f++) acc += Wsc[f] * Ws[f * HH + t];
            ts[t] = acc;
            float inner = 0.f;
            for (int o = 0; o < HH; o++) inner += Ws[t * HH + o] * b2[o];
            ps[t] = Wsc[t] * (inner + bg[t]);
        }
        __syncthreads();
        if (t < HH) {
            float acc = 0.f;
            for (int o = 0; o < HH; o++) acc += ts[o] * W2[o * HH + t];
            g_u[t] = acc;
        }
        if (t == 0) {
            float acc = bsc[0];
            for (int f = 0; f < HH; f++) acc += ps[f];
            g_c0[0] = acc;
        }
    }
}

// ============================================================
// Kernel A: h1 = relu(x @ W1^T + b1), FFMA2 over node-pairs.
// thread: h = t&63 (feature), g = t>>6 owns 8 nodes (4 f32x2 pairs).
// xsT tile transposed [j][node], pad 36 for LDS.128 alignment.
// ============================================================
#define XPAD 36
__global__ __launch_bounds__(256) void mlp1_kernel(const float* __restrict__ x,
                            const float* __restrict__ W1,
                            const float* __restrict__ b1, int N)
{
    extern __shared__ float sm[];
    float* W1T = sm;                 // [j][h] pad 65: 128*65
    float* xsT = sm + FIN * 65;      // [j][node] pad 36: 128*36
    int t = threadIdx.x;

    for (int i = t; i < HH * FIN; i += 256) {
        int h_ = i >> 7, j = i & 127;
        W1T[j * 65 + h_] = W1[i];    // write stride 65 -> conflict-free
    }

    int h = t & 63, g = t >> 6;
    float bb = b1[h];
    int ntiles = (N + 31) >> 5;

    for (int tile = blockIdx.x; tile < ntiles; tile += gridDim.x) {
        int n0 = tile << 5;
        __syncthreads();
        for (int i = t; i < 32 * FIN; i += 256) {
            int n = i >> 7, j = i & 127;
            xsT[j * XPAD + n] = (n0 + n < N) ? x[(size_t)(n0 + n) * FIN + j] : 0.f;
        }
        __syncthreads();

        ull a0 = pack2(bb, bb), a1 = a0, a2 = a0, a3 = a0;

        #pragma unroll 4
        for (int j = 0; j < FIN; j++) {
            float w = W1T[j * 65 + h];
            ull ww = pack2(w, w);
            const ulonglong2* xp = (const ulonglong2*)(xsT + j * XPAD);
            ulonglong2 xa = xp[2 * g];       // nodes 8g..8g+3
            ulonglong2 xb = xp[2 * g + 1];   // nodes 8g+4..8g+7
            ffma2(a0, ww, xa.x);
            ffma2(a1, ww, xa.y);
            ffma2(a2, ww, xb.x);
            ffma2(a3, ww, xb.y);
        }

        int nb = n0 + 8 * g;
        float2 r0 = unpack2(a0), r1 = unpack2(a1), r2 = unpack2(a2), r3 = unpack2(a3);
        float v[8] = {r0.x, r0.y, r1.x, r1.y, r2.x, r2.y, r3.x, r3.y};
        #pragma unroll
        for (int d = 0; d < 8; d++) {
            int n = nb + d;
            if (n < N) g_h1[(size_t)n * HH + h] = fmaxf(v[d], 0.f);
        }
    }
}

// ============================================================
// Kernel B: k,q,vw fused 64x64 projections (FFMA2 over feature
// pairs), writes half2 outputs + scorer init into d_out.
// ============================================================
__global__ __launch_bounds__(256) void proj_kernel(float* __restrict__ out, int N)
{
    extern __shared__ float sm[];
    float* Aks = sm;
    float* Aqs = sm + HH * HH;
    float* Avs = sm + 2 * HH * HH;
    float* h1s = sm + 3 * HH * HH;      // [32][64]
    float* us  = h1s + 32 * HH;
    float* cks = us + HH;
    float* cqs = cks + HH;
    float* cvs = cqs + HH;
    int t = threadIdx.x;

    for (int i = t; i < HH * HH; i += 256) {
        Aks[i] = g_AkT[i]; Aqs[i] = g_AqT[i]; Avs[i] = g_AvT[i];
    }
    if (t < HH) { us[t] = g_u[t]; cks[t] = g_ck[t]; cqs[t] = g_cq[t]; cvs[t] = g_cv[t]; }
    __syncthreads();

    int p = t & 31, g = t >> 5;
    float c0 = g_c0[0];
    float2 ck2 = ((float2*)cks)[p], cq2 = ((float2*)cqs)[p], cv2 = ((float2*)cvs)[p];
    float2 u2  = ((float2*)us)[p];
    int ntiles = (N + 31) >> 5;

    for (int tile = blockIdx.x; tile < ntiles; tile += gridDim.x) {
        int n0 = tile << 5;
        __syncthreads();
        for (int i = t; i < 32 * HH; i += 256) {
            int n = n0 + (i >> 6);
            h1s[i] = (n < N) ? g_h1[(size_t)n0 * HH + i] : 0.f;
        }
        __syncthreads();

        ull kA0 = 0, kA1 = 0, kA2 = 0, kA3 = 0;
        ull qA0 = 0, qA1 = 0, qA2 = 0, qA3 = 0;
        ull wA0 = 0, wA1 = 0, wA2 = 0, wA3 = 0;
        const float* h0  = h1s + (4 * g + 0) * HH;
        const float* h1p = h1s + (4 * g + 1) * HH;
        const float* h2  = h1s + (4 * g + 2) * HH;
        const float* h3  = h1s + (4 * g + 3) * HH;

        #pragma unroll 4
        for (int m = 0; m < HH; m++) {
            ull ak = ((const ull*)(Aks + m * HH))[p];
            ull aq = ((const ull*)(Aqs + m * HH))[p];
            ull av = ((const ull*)(Avs + m * HH))[p];
            ull v0 = pack2(h0[m],  h0[m]);
            ull v1 = pack2(h1p[m], h1p[m]);
            ull v2 = pack2(h2[m],  h2[m]);
            ull v3 = pack2(h3[m],  h3[m]);
            ffma2(kA0, ak, v0); ffma2(kA1, ak, v1); ffma2(kA2, ak, v2); ffma2(kA3, ak, v3);
            ffma2(qA0, aq, v0); ffma2(qA1, aq, v1); ffma2(qA2, aq, v2); ffma2(qA3, aq, v3);
            ffma2(wA0, av, v0); ffma2(wA1, av, v1); ffma2(wA2, av, v2); ffma2(wA3, av, v3);
        }

        int nb = n0 + 4 * g;
        #pragma unroll
        for (int d = 0; d < 4; d++) {
            int n = nb + d;
            if (n >= N) break;
            float2 kf = unpack2(d == 0 ? kA0 : d == 1 ? kA1 : d == 2 ? kA2 : kA3);
            float2 qf = unpack2(d == 0 ? qA0 : d == 1 ? qA1 : d == 2 ? qA2 : qA3);
            float2 wf = unpack2(d == 0 ? wA0 : d == 1 ? wA1 : d == 2 ? wA2 : wA3);
            g_k2 [(size_t)n * 32 + p] = __floats2half2_rn(kf.x + ck2.x, kf.y + ck2.y);
            g_q2 [(size_t)n * 32 + p] = __floats2half2_rn(qf.x + cq2.x, qf.y + cq2.y);
            g_vw2[(size_t)n * 32 + p] = __floats2half2_rn(wf.x + cv2.x, wf.y + cv2.y);
        }

        // scorer init: u . h1[n] + c0
        float s0 = u2.x * h0[2*p]  + u2.y * h0[2*p+1];
        float s1 = u2.x * h1p[2*p] + u2.y * h1p[2*p+1];
        float s2 = u2.x * h2[2*p]  + u2.y * h2[2*p+1];
        float s3 = u2.x * h3[2*p]  + u2.y * h3[2*p+1];
        #pragma unroll
        for (int off = 16; off; off >>= 1) {
            s0 += __shfl_down_sync(0xffffffffu, s0, off);
            s1 += __shfl_down_sync(0xffffffffu, s1, off);
            s2 += __shfl_down_sync(0xffffffffu, s2, off);
            s3 += __shfl_down_sync(0xffffffffu, s3, off);
        }
        if (p == 0) {
            if (nb + 0 < N) out[nb + 0] = s0 + c0;
            if (nb + 1 < N) out[nb + 1] = s1 + c0;
            if (nb + 2 < N) out[nb + 2] = s2 + c0;
            if (nb + 3 < N) out[nb + 3] = s3 + c0;
        }
    }
}

// ============================================================
// Edge kernel: 16 lanes per edge (2 edges/warp), fp16 rows,
// tanh-based sigmoid. One scalar atomic per edge.
// ============================================================
__global__ __launch_bounds__(256) void edge_kernel(const int* __restrict__ ei,
                            float* __restrict__ out, int E)
{
    int lane = threadIdx.x & 31;
    int sl   = lane & 15;     // lane within half-warp
    int sub  = lane >> 4;     // which edge of the pair
    int warp = (blockIdx.x * blockDim.x + threadIdx.x) >> 5;
    int nwarps = (gridDim.x * blockDim.x) >> 5;
    int per = (E + nwarps - 1) / nwarps;
    int e0 = warp * per;
    int e1 = min(E, e0 + per);

    const __half2* __restrict__ kp = g_k2;
    const __half2* __restrict__ qp = g_q2;
    const __half2* __restrict__ vp = g_vw2;

    #pragma unroll 2
    for (int eb = e0; eb < e1; eb += 2) {
        int e = eb + sub;
        bool valid = e < e1;
        int src = valid ? ei[e]     : 0;
        int dst = valid ? ei[E + e] : 0;

        uint2 kk = *((const uint2*)(kp + (size_t)dst * 32) + sl);  // 4 feats/lane
        uint2 qq = *((const uint2*)(qp + (size_t)src * 32) + sl);
        uint2 vv = *((const uint2*)(vp + (size_t)src * 32) + sl);

        __half2 s0 = __hadd2(*(__half2*)&kk.x, *(__half2*)&qq.x);
        __half2 s1 = __hadd2(*(__half2*)&kk.y, *(__half2*)&qq.y);
        float2 sf0 = __half22float2(s0);
        float2 sf1 = __half22float2(s1);
        float2 vf0 = __half22float2(*(__half2*)&vv.x);
        float2 vf1 = __half22float2(*(__half2*)&vv.y);

        // sigmoid(x) = 0.5*tanh(0.5x) + 0.5
        float g0 = fmaf(0.5f, tanh_approx(0.5f * sf0.x), 0.5f);
        float g1 = fmaf(0.5f, tanh_approx(0.5f * sf0.y), 0.5f);
        float g2 = fmaf(0.5f, tanh_approx(0.5f * sf1.x), 0.5f);
        float g3 = fmaf(0.5f, tanh_approx(0.5f * sf1.y), 0.5f);

        float acc = g0 * vf0.x + g1 * vf0.y + g2 * vf1.x + g3 * vf1.y;

        #pragma unroll
        for (int off = 8; off; off >>= 1)
            acc += __shfl_down_sync(0xffffffffu, acc, off, 16);

        if (sl == 0 && valid) atomicAdd(out + dst, acc);
    }
}

// ============================================================
extern "C" void kernel_launch(void* const* d_in, const int* in_sizes, int n_in,
                              void* d_out, int out_size)
{
    const float* x    = (const float*)d_in[0];
    const int*   ei   = (const int*)d_in[1];      // int32 (JAX x64 disabled)
    const float* W1   = (const float*)d_in[2];
    const float* b1   = (const float*)d_in[3];
    const float* W2   = (const float*)d_in[4];
    const float* b2   = (const float*)d_in[5];
    const float* Wk   = (const float*)d_in[6];
    const float* bk   = (const float*)d_in[7];
    const float* Wq   = (const float*)d_in[8];
    const float* bq   = (const float*)d_in[9];
    const float* Wv   = (const float*)d_in[10];
    const float* bv   = (const float*)d_in[11];
    const float* Ws   = (const float*)d_in[12];
    const float* bg   = (const float*)d_in[13];
    const float* Wsc  = (const float*)d_in[14];
    const float* bsc  = (const float*)d_in[15];
    float* out = (float*)d_out;

    int N = in_sizes[0] / FIN;
    int E = in_sizes[1] / 2;

    static int attr_done = 0;
    const int mlp1_smem = (FIN * 65 + FIN * XPAD) * (int)sizeof(float);          // 51712
    const int proj_smem = (3 * HH * HH + 32 * HH + 4 * HH) * (int)sizeof(float); // 58368
    if (!attr_done) {
        cudaFuncSetAttribute(mlp1_kernel, cudaFuncAttributeMaxDynamicSharedMemorySize, mlp1_smem);
        cudaFuncSetAttribute(proj_kernel, cudaFuncAttributeMaxDynamicSharedMemorySize, proj_smem);
        attr_done = 1;
    }

    prep_kernel<<<4, 256>>>(W2, b2, Wk, bk, Wq, bq, Wv, bv, Ws, bg, Wsc, bsc);
    mlp1_kernel<<<592, 256, mlp1_smem>>>(x, W1, b1, N);
    proj_kernel<<<444, 256, proj_smem>>>(out, N);
    edge_kernel<<<1184, 256>>>(ei, out, E);
}

// round 5
// speedup vs baseline: 1.3333x; 1.0884x over previous
#include <cuda_runtime.h>
#include <cuda_fp16.h>
#include <math.h>

#define FIN 128
#define HH  64
#define MAXN 100000
#define MAXE 1600000

typedef unsigned long long ull;

// ---- device scratch (allocation-free rule: __device__ globals) ----
__device__ __half2 g_k2 [MAXN * 32];   // 0.5*(fused key)   fp16: 32 half2 = 64 feats/row
__device__ __half2 g_q2 [MAXN * 32];   // 0.5*(fused query)
__device__ __half2 g_vw2[MAXN * 32];   // fused value pre-scaled by Wsc
__device__ float g_AkT[HH * HH];       // [m][f]
__device__ float g_AqT[HH * HH];
__device__ float g_AvT[HH * HH];
__device__ float g_u  [HH];
__device__ float g_ck [HH];
__device__ float g_cq [HH];
__device__ float g_cv [HH];
__device__ float g_c0 [1];

// ---- packed-math helpers ----
__device__ __forceinline__ void ffma2(ull& d, ull a, ull b) {
    asm("fma.rn.f32x2 %0, %1, %2, %0;" : "+l"(d) : "l"(a), "l"(b));
}
__device__ __forceinline__ ull pack2(float x, float y) {
    ull r; asm("mov.b64 %0, {%1, %2};" : "=l"(r) : "f"(x), "f"(y)); return r;
}
__device__ __forceinline__ float2 unpack2(ull v) {
    float2 r; asm("mov.b64 {%0, %1}, %2;" : "=f"(r.x), "=f"(r.y) : "l"(v)); return r;
}
__device__ __forceinline__ unsigned h2tanh(unsigned x) {
    unsigned r; asm("tanh.approx.f16x2 %0, %1;" : "=r"(r) : "r"(x)); return r;
}

// ============================================================
// Prep: fold W2 into projections. 4 blocks, one per matrix/task.
// ============================================================
__global__ void prep_kernel(const float* __restrict__ W2, const float* __restrict__ b2,
                            const float* __restrict__ Wk, const float* __restrict__ bk,
                            const float* __restrict__ Wq, const float* __restrict__ bq,
                            const float* __restrict__ Wv, const float* __restrict__ bv,
                            const float* __restrict__ Ws, const float* __restrict__ bg,
                            const float* __restrict__ Wsc, const float* __restrict__ bsc)
{
    __shared__ float WaT[HH * HH];   // [o][f]
    __shared__ float W2s[HH * HH];   // [o][m]
    int t = threadIdx.x;             // 256
    int b = blockIdx.x;

    if (b < 3) {
        const float* Wa  = (b == 0) ? Wk : (b == 1) ? Wq : Wv;
        const float* bia = (b == 0) ? bk : (b == 1) ? bq : bv;
        float* outA = (b == 0) ? g_AkT : (b == 1) ? g_AqT : g_AvT;
        float* outc = (b == 0) ? g_ck  : (b == 1) ? g_cq  : g_cv;

        for (int i = t; i < HH * HH; i += 256) {
            int f = i / HH, o = i % HH;
            WaT[o * HH + f] = Wa[i];
            W2s[i] = W2[i];
        }
        __syncthreads();
        for (int i = t; i < HH * HH; i += 256) {
            int m = i >> 6, f = i & 63;
            float acc = 0.f;
            #pragma unroll 8
            for (int o = 0; o < HH; o++)
                acc += WaT[o * HH + f] * W2s[o * HH + m];
            if (b == 2) acc *= Wsc[f];
            outA[m * HH + f] = acc;
        }
        if (t < HH) {
            float acc = 0.f;
            for (int o = 0; o < HH; o++) acc += WaT[o * HH + t] * b2[o];
            acc += bia[t];
            if (b == 2) acc *= Wsc[t];
            outc[t] = acc;
        }
    } else {
        __shared__ float ts[HH];
        __shared__ float ps[HH];
        if (t < HH) {
            float acc = 0.f;
            for (int f = 0; f < HH; f++) acc += Wsc[f] * Ws[f * HH + t];
            ts[t] = acc;
            float inner = 0.f;
            for (int o = 0; o < HH; o++) inner += Ws[t * HH + o] * b2[o];
            ps[t] = Wsc[t] * (inner + bg[t]);
        }
        __syncthreads();
        if (t < HH) {
            float acc = 0.f;
            for (int o = 0; o < HH; o++) acc += ts[o] * W2[o * HH + t];
            g_u[t] = acc;
        }
        if (t == 0) {
            float acc = bsc[0];
            for (int f = 0; f < HH; f++) acc += ps[f];
            g_c0[0] = acc;
        }
    }
}

// ============================================================
// Fused node kernel: per 32-node tile
//   phase 1: h1 = relu(x @ W1^T + b1)  -> smem (never hits DRAM)
//   phase 2: k,q,vw projections (FFMA2) -> fp16 (k,q pre-halved)
//            + scorer init into d_out
// ============================================================
#define XPAD 36
// smem layout (floats):
//   W1T  [0, 128*65)                = 8320
//   Aks  [8320, +4096), Aqs, Avs    -> ends 20608
//   xsT  [20608, +128*36=4608)      -> ends 25216
//   h1s  [25216, +32*64=2048)       -> ends 27264
//   us/cks/cqs/cvs [27264, +256)    -> ends 27520
#define SM_W1T   0
#define SM_AK    8320
#define SM_AQ    (8320 + 4096)
#define SM_AV    (8320 + 8192)
#define SM_XST   20608
#define SM_H1    25216
#define SM_CON   27264
#define NODE_SMEM_FLOATS 27520

__global__ __launch_bounds__(256, 2) void node_kernel(const float* __restrict__ x,
                            const float* __restrict__ W1,
                            const float* __restrict__ b1,
                            float* __restrict__ out, int N)
{
    extern __shared__ float sm[];
    float* W1T = sm + SM_W1T;
    float* Aks = sm + SM_AK;
    float* Aqs = sm + SM_AQ;
    float* Avs = sm + SM_AV;
    float* xsT = sm + SM_XST;
    float* h1s = sm + SM_H1;
    float* us  = sm + SM_CON;
    float* cks = us + HH;
    float* cqs = cks + HH;
    float* cvs = cqs + HH;
    int t = threadIdx.x;

    for (int i = t; i < HH * FIN; i += 256) {
        int h_ = i >> 7, j = i & 127;
        W1T[j * 65 + h_] = W1[i];       // stride-65 -> conflict-free
    }
    for (int i = t; i < HH * HH; i += 256) {
        Aks[i] = g_AkT[i]; Aqs[i] = g_AqT[i]; Avs[i] = g_AvT[i];
    }
    if (t < HH) { us[t] = g_u[t]; cks[t] = g_ck[t]; cqs[t] = g_cq[t]; cvs[t] = g_cv[t]; }
    __syncthreads();

    int h  = t & 63, gm = t >> 6;     // mlp phase: feature h, node-group gm (8 nodes)
    int p  = t & 31, g  = t >> 5;     // proj phase: feat-pair p, node-group g (4 nodes)
    float bb  = b1[h];
    float c0  = g_c0[0];
    float2 ck2 = ((float2*)cks)[p], cq2 = ((float2*)cqs)[p], cv2 = ((float2*)cvs)[p];
    float2 u2  = ((float2*)us)[p];
    int ntiles = (N + 31) >> 5;

    for (int tile = blockIdx.x; tile < ntiles; tile += gridDim.x) {
        int n0 = tile << 5;
        __syncthreads();
        for (int i = t; i < 32 * FIN; i += 256) {
            int n = i >> 7, j = i & 127;
            xsT[j * XPAD + n] = (n0 + n < N) ? x[(size_t)(n0 + n) * FIN + j] : 0.f;
        }
        __syncthreads();

        // ---- phase 1: mlp1 (FFMA2 over node-pairs) ----
        {
            ull a0 = pack2(bb, bb), a1 = a0, a2 = a0, a3 = a0;
            #pragma unroll 4
            for (int j = 0; j < FIN; j++) {
                float w = W1T[j * 65 + h];
                ull ww = pack2(w, w);
                const ulonglong2* xp = (const ulonglong2*)(xsT + j * XPAD);
                ulonglong2 xa = xp[2 * gm];       // nodes 8gm..8gm+3
                ulonglong2 xb = xp[2 * gm + 1];   // nodes 8gm+4..8gm+7
                ffma2(a0, ww, xa.x);
                ffma2(a1, ww, xa.y);
                ffma2(a2, ww, xb.x);
                ffma2(a3, ww, xb.y);
            }
            float2 r0 = unpack2(a0), r1 = unpack2(a1), r2 = unpack2(a2), r3 = unpack2(a3);
            int nb = 8 * gm;
            h1s[(nb+0)*HH + h] = fmaxf(r0.x, 0.f);
            h1s[(nb+1)*HH + h] = fmaxf(r0.y, 0.f);
            h1s[(nb+2)*HH + h] = fmaxf(r1.x, 0.f);
            h1s[(nb+3)*HH + h] = fmaxf(r1.y, 0.f);
            h1s[(nb+4)*HH + h] = fmaxf(r2.x, 0.f);
            h1s[(nb+5)*HH + h] = fmaxf(r2.y, 0.f);
            h1s[(nb+6)*HH + h] = fmaxf(r3.x, 0.f);
            h1s[(nb+7)*HH + h] = fmaxf(r3.y, 0.f);
        }
        __syncthreads();

        // ---- phase 2: projections ----
        ull kA0 = 0, kA1 = 0, kA2 = 0, kA3 = 0;
        ull qA0 = 0, qA1 = 0, qA2 = 0, qA3 = 0;
        ull wA0 = 0, wA1 = 0, wA2 = 0, wA3 = 0;
        const float* h0  = h1s + (4 * g + 0) * HH;
        const float* h1p = h1s + (4 * g + 1) * HH;
        const float* h2  = h1s + (4 * g + 2) * HH;
        const float* h3  = h1s + (4 * g + 3) * HH;

        #pragma unroll 4
        for (int m = 0; m < HH; m++) {
            ull ak = ((const ull*)(Aks + m * HH))[p];
            ull aq = ((const ull*)(Aqs + m * HH))[p];
            ull av = ((const ull*)(Avs + m * HH))[p];
            ull v0 = pack2(h0[m],  h0[m]);
            ull v1 = pack2(h1p[m], h1p[m]);
            ull v2 = pack2(h2[m],  h2[m]);
            ull v3 = pack2(h3[m],  h3[m]);
            ffma2(kA0, ak, v0); ffma2(kA1, ak, v1); ffma2(kA2, ak, v2); ffma2(kA3, ak, v3);
            ffma2(qA0, aq, v0); ffma2(qA1, aq, v1); ffma2(qA2, aq, v2); ffma2(qA3, aq, v3);
            ffma2(wA0, av, v0); ffma2(wA1, av, v1); ffma2(wA2, av, v2); ffma2(wA3, av, v3);
        }

        int nb = n0 + 4 * g;
        #pragma unroll
        for (int d = 0; d < 4; d++) {
            int n = nb + d;
            if (n >= N) break;
            float2 kf = unpack2(d == 0 ? kA0 : d == 1 ? kA1 : d == 2 ? kA2 : kA3);
            float2 qf = unpack2(d == 0 ? qA0 : d == 1 ? qA1 : d == 2 ? qA2 : qA3);
            float2 wf = unpack2(d == 0 ? wA0 : d == 1 ? wA1 : d == 2 ? wA2 : wA3);
            // store HALF of k and q: gate = 0.5*tanh(khalf+qhalf)+0.5
            g_k2 [(size_t)n * 32 + p] = __floats2half2_rn(0.5f*(kf.x + ck2.x), 0.5f*(kf.y + ck2.y));
            g_q2 [(size_t)n * 32 + p] = __floats2half2_rn(0.5f*(qf.x + cq2.x), 0.5f*(qf.y + cq2.y));
            g_vw2[(size_t)n * 32 + p] = __floats2half2_rn(wf.x + cv2.x, wf.y + cv2.y);
        }

        // scorer init: u . h1[n] + c0
        float s0 = u2.x * h0[2*p]  + u2.y * h0[2*p+1];
        float s1 = u2.x * h1p[2*p] + u2.y * h1p[2*p+1];
        float s2 = u2.x * h2[2*p]  + u2.y * h2[2*p+1];
        float s3 = u2.x * h3[2*p]  + u2.y * h3[2*p+1];
        #pragma unroll
        for (int off = 16; off; off >>= 1) {
            s0 += __shfl_down_sync(0xffffffffu, s0, off);
            s1 += __shfl_down_sync(0xffffffffu, s1, off);
            s2 += __shfl_down_sync(0xffffffffu, s2, off);
            s3 += __shfl_down_sync(0xffffffffu, s3, off);
        }
        if (p == 0) {
            if (nb + 0 < N) out[nb + 0] = s0 + c0;
            if (nb + 1 < N) out[nb + 1] = s1 + c0;
            if (nb + 2 < N) out[nb + 2] = s2 + c0;
            if (nb + 3 < N) out[nb + 3] = s3 + c0;
        }
    }
}

// ============================================================
// Edge kernel: 8 lanes per edge (4 edges/warp), full fp16 path.
//   gate = 0.5*tanh(khalf[dst]+qhalf[src]) + 0.5   (tanh.approx.f16x2)
//   out[dst] += sum_f gate_f * vw[src]_f           (hfma2 dot)
// ============================================================
__global__ __launch_bounds__(256) void edge_kernel(const int* __restrict__ ei,
                            float* __restrict__ out, int E)
{
    int lane = threadIdx.x & 31;
    int sl   = lane & 7;      // lane within 8-group
    int sub  = lane >> 3;     // which of 4 edges
    int warp = (blockIdx.x * blockDim.x + threadIdx.x) >> 5;
    int nwarps = (gridDim.x * blockDim.x) >> 5;
    int per = (E + nwarps - 1) / nwarps;
    int e0 = warp * per;
    int e1 = min(E, e0 + per);

    const __half2 c05 = __float2half2_rn(0.5f);

    for (int eb = e0; eb < e1; eb += 4) {
        int e = eb + sub;
        bool valid = e < e1;
        int src = valid ? ei[e]     : 0;
        int dst = valid ? ei[E + e] : 0;

        uint4 kk = *((const uint4*)(g_k2  + (size_t)dst * 32) + sl);  // 8 feats/lane
        uint4 qq = *((const uint4*)(g_q2  + (size_t)src * 32) + sl);
        uint4 vv = *((const uint4*)(g_vw2 + (size_t)src * 32) + sl);

        __half2 acc2 = __float2half2_rn(0.f);
        {
            __half2 s, gt;
            unsigned ts_;
            s = __hadd2(*(__half2*)&kk.x, *(__half2*)&qq.x);
            ts_ = h2tanh(*(unsigned*)&s); gt = __hfma2(*(__half2*)&ts_, c05, c05);
            acc2 = __hfma2(gt, *(__half2*)&vv.x, acc2);

            s = __hadd2(*(__half2*)&kk.y, *(__half2*)&qq.y);
            ts_ = h2tanh(*(unsigned*)&s); gt = __hfma2(*(__half2*)&ts_, c05, c05);
            acc2 = __hfma2(gt, *(__half2*)&vv.y, acc2);

            s = __hadd2(*(__half2*)&kk.z, *(__half2*)&qq.z);
            ts_ = h2tanh(*(unsigned*)&s); gt = __hfma2(*(__half2*)&ts_, c05, c05);
            acc2 = __hfma2(gt, *(__half2*)&vv.z, acc2);

            s = __hadd2(*(__half2*)&kk.w, *(__half2*)&qq.w);
            ts_ = h2tanh(*(unsigned*)&s); gt = __hfma2(*(__half2*)&ts_, c05, c05);
            acc2 = __hfma2(gt, *(__half2*)&vv.w, acc2);
        }
        float acc = __low2float(acc2) + __high2float(acc2);

        #pragma unroll
        for (int off = 4; off; off >>= 1)
            acc += __shfl_down_sync(0xffffffffu, acc, off, 8);

        if (sl == 0 && valid) atomicAdd(out + dst, acc);
    }
}

// ============================================================
extern "C" void kernel_launch(void* const* d_in, const int* in_sizes, int n_in,
                              void* d_out, int out_size)
{
    const float* x    = (const float*)d_in[0];
    const int*   ei   = (const int*)d_in[1];      // int32 (JAX x64 disabled)
    const float* W1   = (const float*)d_in[2];
    const float* b1   = (const float*)d_in[3];
    const float* W2   = (const float*)d_in[4];
    const float* b2   = (const float*)d_in[5];
    const float* Wk   = (const float*)d_in[6];
    const float* bk   = (const float*)d_in[7];
    const float* Wq   = (const float*)d_in[8];
    const float* bq   = (const float*)d_in[9];
    const float* Wv   = (const float*)d_in[10];
    const float* bv   = (const float*)d_in[11];
    const float* Ws   = (const float*)d_in[12];
    const float* bg   = (const float*)d_in[13];
    const float* Wsc  = (const float*)d_in[14];
    const float* bsc  = (const float*)d_in[15];
    float* out = (float*)d_out;

    int N = in_sizes[0] / FIN;
    int E = in_sizes[1] / 2;

    static int attr_done = 0;
    const int node_smem = NODE_SMEM_FLOATS * (int)sizeof(float);   // 110080
    if (!attr_done) {
        cudaFuncSetAttribute(node_kernel, cudaFuncAttributeMaxDynamicSharedMemorySize, node_smem);
        attr_done = 1;
    }

    prep_kernel<<<4, 256>>>(W2, b2, Wk, bk, Wq, bq, Wv, bv, Ws, bg, Wsc, bsc);
    node_kernel<<<296, 256, node_smem>>>(x, W1, b1, out, N);
    edge_kernel<<<1184, 256>>>(ei, out, E);
}

// round 6
// speedup vs baseline: 1.3442x; 1.0082x over previous
#include <cuda_runtime.h>
#include <cuda_fp16.h>
#include <math.h>

#define FIN 128
#define HH  64
#define MAXN 100000
#define MAXE 1600000

typedef unsigned long long ull;

// ---- device scratch (allocation-free rule: __device__ globals) ----
__device__ __half2 g_k2 [MAXN * 32];   // 0.5*(fused key)   fp16: 32 half2 = 64 feats/row
__device__ __half2 g_q2 [MAXN * 32];   // 0.5*(fused query)
__device__ __half2 g_vw2[MAXN * 32];   // fused value pre-scaled by Wsc
__device__ float g_AkT[HH * HH];       // [m][f], pre-scaled by 0.5
__device__ float g_AqT[HH * HH];       // pre-scaled by 0.5
__device__ float g_AvT[HH * HH];       // pre-scaled by Wsc[f]
__device__ float g_u  [HH];
__device__ float g_ck [HH];            // pre-scaled by 0.5
__device__ float g_cq [HH];            // pre-scaled by 0.5
__device__ float g_cv [HH];            // pre-scaled by Wsc[f]
__device__ float g_c0 [1];

// ---- packed-math helpers ----
__device__ __forceinline__ void ffma2(ull& d, ull a, ull b) {
    asm("fma.rn.f32x2 %0, %1, %2, %0;" : "+l"(d) : "l"(a), "l"(b));
}
__device__ __forceinline__ ull pack2(float x, float y) {
    ull r; asm("mov.b64 %0, {%1, %2};" : "=l"(r) : "f"(x), "f"(y)); return r;
}
__device__ __forceinline__ float2 unpack2(ull v) {
    float2 r; asm("mov.b64 {%0, %1}, %2;" : "=f"(r.x), "=f"(r.y) : "l"(v)); return r;
}
__device__ __forceinline__ unsigned h2tanh(unsigned x) {
    unsigned r; asm("tanh.approx.f16x2 %0, %1;" : "=r"(r) : "r"(x)); return r;
}

// ============================================================
// Prep (wide): fold W2 into projections.
// Blocks 0..47: matrix blocks (16 per matrix, 4 m-rows each).
// Block 48: scorer head (u, c0).
// k,q outputs pre-scaled by 0.5 (tanh-gate form); v by Wsc.
// ============================================================
__global__ void prep_kernel(const float* __restrict__ W2, const float* __restrict__ b2,
                            const float* __restrict__ Wk, const float* __restrict__ bk,
                            const float* __restrict__ Wq, const float* __restrict__ bq,
                            const float* __restrict__ Wv, const float* __restrict__ bv,
                            const float* __restrict__ Ws, const float* __restrict__ bg,
                            const float* __restrict__ Wsc, const float* __restrict__ bsc)
{
    int b = blockIdx.x;
    int t = threadIdx.x;             // 256

    if (b < 48) {
        int mat    = b >> 4;         // 0=k, 1=q, 2=v
        int mslice = b & 15;         // 4 m-rows per block
        const float* Wa  = (mat == 0) ? Wk : (mat == 1) ? Wq : Wv;
        const float* bia = (mat == 0) ? bk : (mat == 1) ? bq : bv;
        float* outA = (mat == 0) ? g_AkT : (mat == 1) ? g_AqT : g_AvT;
        float* outc = (mat == 0) ? g_ck  : (mat == 1) ? g_cq  : g_cv;

        __shared__ float WaS[HH * 65];   // [f][o] pad-65 (conflict-free col reads)
        __shared__ float W2c[HH * 4];    // [o][mi]
        __shared__ float scl[HH];        // per-f output scale

        for (int i = t; i < HH * HH; i += 256) {
            int f = i >> 6, o = i & 63;
            WaS[f * 65 + o] = Wa[i];
        }
        {
            int o = t >> 2, mi = t & 3;
            int m0 = mslice * 4;
            W2c[o * 4 + mi] = W2[o * HH + m0 + mi];
        }
        if (t < HH) scl[t] = (mat == 2) ? Wsc[t] : 0.5f;
        __syncthreads();

        int f = t & 63, mi = t >> 6;
        float acc = 0.f;
        #pragma unroll 8
        for (int o = 0; o < HH; o++)
            acc += WaS[f * 65 + o] * W2c[o * 4 + mi];
        int m0 = mslice * 4;
        outA[(m0 + mi) * HH + f] = acc * scl[f];

        if (mslice == 0 && t < HH) {
            float a = 0.f;
            #pragma unroll 8
            for (int o = 0; o < HH; o++) a += WaS[t * 65 + o] * b2[o];
            a += bia[t];
            outc[t] = a * scl[t];
        }
    } else {
        // u[m] = sum_o (sum_f Wsc[f]*Ws[f][o]) * W2[o][m];  c0 scalar
        __shared__ float ts[HH];
        __shared__ float ps[HH];
        if (t < HH) {
            float acc = 0.f;
            #pragma unroll 8
            for (int f = 0; f < HH; f++) acc += Wsc[f] * Ws[f * HH + t];
            ts[t] = acc;
            float inner = 0.f;
            #pragma unroll 8
            for (int o = 0; o < HH; o++) inner += Ws[t * HH + o] * b2[o];
            ps[t] = Wsc[t] * (inner + bg[t]);
        }
        __syncthreads();
        if (t < HH) {
            float acc = 0.f;
            #pragma unroll 8
            for (int o = 0; o < HH; o++) acc += ts[o] * W2[o * HH + t];
            g_u[t] = acc;
        }
        if (t == 0) {
            float acc = bsc[0];
            for (int f = 0; f < HH; f++) acc += ps[f];
            g_c0[0] = acc;
        }
    }
}

// ============================================================
// Fused node kernel: per 32-node tile
//   phase 1: h1 = relu(x @ W1^T + b1)  -> smem
//   phase 2: k,q,vw projections (FFMA2) -> fp16 + scorer init
// ============================================================
#define XPAD 36
#define SM_W1T   0
#define SM_AK    8320
#define SM_AQ    (8320 + 4096)
#define SM_AV    (8320 + 8192)
#define SM_XST   20608
#define SM_H1    25216
#define SM_CON   27264
#define NODE_SMEM_FLOATS 27520

__global__ __launch_bounds__(256, 2) void node_kernel(const float* __restrict__ x,
                            const float* __restrict__ W1,
                            const float* __restrict__ b1,
                            float* __restrict__ out, int N)
{
    extern __shared__ float sm[];
    float* W1T = sm + SM_W1T;
    float* Aks = sm + SM_AK;
    float* Aqs = sm + SM_AQ;
    float* Avs = sm + SM_AV;
    float* xsT = sm + SM_XST;
    float* h1s = sm + SM_H1;
    float* us  = sm + SM_CON;
    float* cks = us + HH;
    float* cqs = cks + HH;
    float* cvs = cqs + HH;
    int t = threadIdx.x;

    for (int i = t; i < HH * FIN; i += 256) {
        int h_ = i >> 7, j = i & 127;
        W1T[j * 65 + h_] = W1[i];       // stride-65 -> conflict-free
    }
    for (int i = t; i < HH * HH; i += 256) {
        Aks[i] = g_AkT[i]; Aqs[i] = g_AqT[i]; Avs[i] = g_AvT[i];
    }
    if (t < HH) { us[t] = g_u[t]; cks[t] = g_ck[t]; cqs[t] = g_cq[t]; cvs[t] = g_cv[t]; }
    __syncthreads();

    int h  = t & 63, gm = t >> 6;     // mlp phase: feature h, node-group gm (8 nodes)
    int p  = t & 31, g  = t >> 5;     // proj phase: feat-pair p, node-group g (4 nodes)
    float bb  = b1[h];
    float c0  = g_c0[0];
    float2 ck2 = ((float2*)cks)[p], cq2 = ((float2*)cqs)[p], cv2 = ((float2*)cvs)[p];
    float2 u2  = ((float2*)us)[p];
    int ntiles = (N + 31) >> 5;

    for (int tile = blockIdx.x; tile < ntiles; tile += gridDim.x) {
        int n0 = tile << 5;
        __syncthreads();
        for (int i = t; i < 32 * FIN; i += 256) {
            int n = i >> 7, j = i & 127;
            xsT[j * XPAD + n] = (n0 + n < N) ? x[(size_t)(n0 + n) * FIN + j] : 0.f;
        }
        __syncthreads();

        // ---- phase 1: mlp1 (FFMA2 over node-pairs) ----
        {
            ull a0 = pack2(bb, bb), a1 = a0, a2 = a0, a3 = a0;
            #pragma unroll 4
            for (int j = 0; j < FIN; j++) {
                float w = W1T[j * 65 + h];
                ull ww = pack2(w, w);
                const ulonglong2* xp = (const ulonglong2*)(xsT + j * XPAD);
                ulonglong2 xa = xp[2 * gm];
                ulonglong2 xb = xp[2 * gm + 1];
                ffma2(a0, ww, xa.x);
                ffma2(a1, ww, xa.y);
                ffma2(a2, ww, xb.x);
                ffma2(a3, ww, xb.y);
            }
            float2 r0 = unpack2(a0), r1 = unpack2(a1), r2 = unpack2(a2), r3 = unpack2(a3);
            int nb = 8 * gm;
            h1s[(nb+0)*HH + h] = fmaxf(r0.x, 0.f);
            h1s[(nb+1)*HH + h] = fmaxf(r0.y, 0.f);
            h1s[(nb+2)*HH + h] = fmaxf(r1.x, 0.f);
            h1s[(nb+3)*HH + h] = fmaxf(r1.y, 0.f);
            h1s[(nb+4)*HH + h] = fmaxf(r2.x, 0.f);
            h1s[(nb+5)*HH + h] = fmaxf(r2.y, 0.f);
            h1s[(nb+6)*HH + h] = fmaxf(r3.x, 0.f);
            h1s[(nb+7)*HH + h] = fmaxf(r3.y, 0.f);
        }
        __syncthreads();

        // ---- phase 2: projections ----
        ull kA0 = 0, kA1 = 0, kA2 = 0, kA3 = 0;
        ull qA0 = 0, qA1 = 0, qA2 = 0, qA3 = 0;
        ull wA0 = 0, wA1 = 0, wA2 = 0, wA3 = 0;
        const float* h0  = h1s + (4 * g + 0) * HH;
        const float* h1p = h1s + (4 * g + 1) * HH;
        const float* h2  = h1s + (4 * g + 2) * HH;
        const float* h3  = h1s + (4 * g + 3) * HH;

        #pragma unroll 4
        for (int m = 0; m < HH; m++) {
            ull ak = ((const ull*)(Aks + m * HH))[p];
            ull aq = ((const ull*)(Aqs + m * HH))[p];
            ull av = ((const ull*)(Avs + m * HH))[p];
            ull v0 = pack2(h0[m],  h0[m]);
            ull v1 = pack2(h1p[m], h1p[m]);
            ull v2 = pack2(h2[m],  h2[m]);
            ull v3 = pack2(h3[m],  h3[m]);
            ffma2(kA0, ak, v0); ffma2(kA1, ak, v1); ffma2(kA2, ak, v2); ffma2(kA3, ak, v3);
            ffma2(qA0, aq, v0); ffma2(qA1, aq, v1); ffma2(qA2, aq, v2); ffma2(qA3, aq, v3);
            ffma2(wA0, av, v0); ffma2(wA1, av, v1); ffma2(wA2, av, v2); ffma2(wA3, av, v3);
        }

        int nb = n0 + 4 * g;
        #pragma unroll
        for (int d = 0; d < 4; d++) {
            int n = nb + d;
            if (n >= N) break;
            float2 kf = unpack2(d == 0 ? kA0 : d == 1 ? kA1 : d == 2 ? kA2 : kA3);
            float2 qf = unpack2(d == 0 ? qA0 : d == 1 ? qA1 : d == 2 ? qA2 : qA3);
            float2 wf = unpack2(d == 0 ? wA0 : d == 1 ? wA1 : d == 2 ? wA2 : wA3);
            // Ak/Aq/ck/cq already pre-scaled by 0.5 in prep
            g_k2 [(size_t)n * 32 + p] = __floats2half2_rn(kf.x + ck2.x, kf.y + ck2.y);
            g_q2 [(size_t)n * 32 + p] = __floats2half2_rn(qf.x + cq2.x, qf.y + cq2.y);
            g_vw2[(size_t)n * 32 + p] = __floats2half2_rn(wf.x + cv2.x, wf.y + cv2.y);
        }

        // scorer init: u . h1[n] + c0
        float s0 = u2.x * h0[2*p]  + u2.y * h0[2*p+1];
        float s1 = u2.x * h1p[2*p] + u2.y * h1p[2*p+1];
        float s2 = u2.x * h2[2*p]  + u2.y * h2[2*p+1];
        float s3 = u2.x * h3[2*p]  + u2.y * h3[2*p+1];
        #pragma unroll
        for (int off = 16; off; off >>= 1) {
            s0 += __shfl_down_sync(0xffffffffu, s0, off);
            s1 += __shfl_down_sync(0xffffffffu, s1, off);
            s2 += __shfl_down_sync(0xffffffffu, s2, off);
            s3 += __shfl_down_sync(0xffffffffu, s3, off);
        }
        if (p == 0) {
            if (nb + 0 < N) out[nb + 0] = s0 + c0;
            if (nb + 1 < N) out[nb + 1] = s1 + c0;
            if (nb + 2 < N) out[nb + 2] = s2 + c0;
            if (nb + 3 < N) out[nb + 3] = s3 + c0;
        }
    }
}

// ============================================================
// Edge kernel: 8 lanes per edge (4 edges/warp), full fp16 path,
// software-pipelined index loads (break LDG(idx)->LDG(row) chain).
// ============================================================
__global__ __launch_bounds__(256) void edge_kernel(const int* __restrict__ ei,
                            float* __restrict__ out, int E)
{
    int lane = threadIdx.x & 31;
    int sl   = lane & 7;      // lane within 8-group
    int sub  = lane >> 3;     // which of 4 edges
    int warp = (blockIdx.x * blockDim.x + threadIdx.x) >> 5;
    int nwarps = (gridDim.x * blockDim.x) >> 5;
    int per = (E + nwarps - 1) / nwarps;
    int e0 = warp * per;
    int e1 = min(E, e0 + per);

    const __half2 c05 = __float2half2_rn(0.5f);

    int src = 0, dst = 0;
    {
        int e = e0 + sub;
        if (e < e1) { src = ei[e]; dst = ei[E + e]; }
    }

    for (int eb = e0; eb < e1; eb += 4) {
        int csrc = src, cdst = dst;
        bool valid = (eb + sub) < e1;

        int en = eb + 4 + sub;          // prefetch next quad's indices
        if (en < e1) { src = ei[en]; dst = ei[E + en]; }

        uint4 kk = *((const uint4*)(g_k2  + (size_t)cdst * 32) + sl);  // 8 feats/lane
        uint4 qq = *((const uint4*)(g_q2  + (size_t)csrc * 32) + sl);
        uint4 vv = *((const uint4*)(g_vw2 + (size_t)csrc * 32) + sl);

        __half2 acc2 = __float2half2_rn(0.f);
        {
            __half2 s, gt;
            unsigned ts_;
            s = __hadd2(*(__half2*)&kk.x, *(__half2*)&qq.x);
            ts_ = h2tanh(*(unsigned*)&s); gt = __hfma2(*(__half2*)&ts_, c05, c05);
            acc2 = __hfma2(gt, *(__half2*)&vv.x, acc2);

            s = __hadd2(*(__half2*)&kk.y, *(__half2*)&qq.y);
            ts_ = h2tanh(*(unsigned*)&s); gt = __hfma2(*(__half2*)&ts_, c05, c05);
            acc2 = __hfma2(gt, *(__half2*)&vv.y, acc2);

            s = __hadd2(*(__half2*)&kk.z, *(__half2*)&qq.z);
            ts_ = h2tanh(*(unsigned*)&s); gt = __hfma2(*(__half2*)&ts_, c05, c05);
            acc2 = __hfma2(gt, *(__half2*)&vv.z, acc2);

            s = __hadd2(*(__half2*)&kk.w, *(__half2*)&qq.w);
            ts_ = h2tanh(*(unsigned*)&s); gt = __hfma2(*(__half2*)&ts_, c05, c05);
            acc2 = __hfma2(gt, *(__half2*)&vv.w, acc2);
        }
        float acc = __low2float(acc2) + __high2float(acc2);

        #pragma unroll
        for (int off = 4; off; off >>= 1)
            acc += __shfl_down_sync(0xffffffffu, acc, off, 8);

        if (sl == 0 && valid) atomicAdd(out + cdst, acc);
    }
}

// ============================================================
extern "C" void kernel_launch(void* const* d_in, const int* in_sizes, int n_in,
                              void* d_out, int out_size)
{
    const float* x    = (const float*)d_in[0];
    const int*   ei   = (const int*)d_in[1];      // int32 (JAX x64 disabled)
    const float* W1   = (const float*)d_in[2];
    const float* b1   = (const float*)d_in[3];
    const float* W2   = (const float*)d_in[4];
    const float* b2   = (const float*)d_in[5];
    const float* Wk   = (const float*)d_in[6];
    const float* bk   = (const float*)d_in[7];
    const float* Wq   = (const float*)d_in[8];
    const float* bq   = (const float*)d_in[9];
    const float* Wv   = (const float*)d_in[10];
    const float* bv   = (const float*)d_in[11];
    const float* Ws   = (const float*)d_in[12];
    const float* bg   = (const float*)d_in[13];
    const float* Wsc  = (const float*)d_in[14];
    const float* bsc  = (const float*)d_in[15];
    float* out = (float*)d_out;

    int N = in_sizes[0] / FIN;
    int E = in_sizes[1] / 2;

    static int attr_done = 0;
    const int node_smem = NODE_SMEM_FLOATS * (int)sizeof(float);   // 110080
    if (!attr_done) {
        cudaFuncSetAttribute(node_kernel, cudaFuncAttributeMaxDynamicSharedMemorySize, node_smem);
        attr_done = 1;
    }

    prep_kernel<<<49, 256>>>(W2, b2, Wk, bk, Wq, bq, Wv, bv, Ws, bg, Wsc, bsc);
    node_kernel<<<296, 256, node_smem>>>(x, W1, b1, out, N);
    edge_kernel<<<1184, 256>>>(ei, out, E);
}